// round 16
// baseline (speedup 1.0000x reference)
#include <cuda_runtime.h>
#include <cuda_bf16.h>
#include <cuda_fp16.h>
#include <cstdint>

#define LDIM 512
#define CDIM 128
#define NROWS (LDIM * LDIM)   // 262144 pair rows
#define EPSV 1e-5f

// ---------------- scratch (static device memory; no runtime allocation) ----
__device__ float d_g  [(size_t)NROWS * CDIM];      // sigmoid(zln @ W_gate_out), [n][c]
__device__ __half d_a16[(size_t)CDIM * NROWS];     // a fp16: [c][i][k]
__device__ __half d_b16[(size_t)CDIM * NROWS];     // b fp16: [c][j][k]
__device__ float d_mt [(size_t)CDIM * NROWS];      // einsum result: [c][i][j]
// pre-transposed weights [w][ch][k] fp16; slots: Wga,Wpa,Wgb,Wpb,Wgo,Wpo
__device__ __half d_w16[6 * CDIM * CDIM];

// ---------------- arch-generic PTX helpers (plain sm_103 target!) ----------
__device__ __forceinline__ uint32_t smem_u32(const void* p) {
  uint32_t a;
  asm("{ .reg .u64 t; cvta.to.shared.u64 t, %1; cvt.u32.u64 %0, t; }" : "=r"(a) : "l"(p));
  return a;
}
#define CP_ASYNC16(s, g) \
  asm volatile("cp.async.cg.shared.global [%0], [%1], 16;" :: "r"(s), "l"(g) : "memory")
#define CP_COMMIT() asm volatile("cp.async.commit_group;" ::: "memory")
#define CP_WAIT(n)  asm volatile("cp.async.wait_group %0;" :: "n"(n) : "memory")

#define LDSM_X4(r0, r1, r2, r3, addr) \
  asm volatile("ldmatrix.sync.aligned.m8n8.x4.shared.b16 {%0,%1,%2,%3}, [%4];" \
    : "=r"(r0), "=r"(r1), "=r"(r2), "=r"(r3) : "r"(addr))

#define MMAH16816(d, a, b0, b1) \
  asm volatile("mma.sync.aligned.m16n8k16.row.col.f32.f16.f16.f32 " \
    "{%0,%1,%2,%3}, {%4,%5,%6,%7}, {%8,%9}, {%0,%1,%2,%3};" \
    : "+f"((d)[0]), "+f"((d)[1]), "+f"((d)[2]), "+f"((d)[3]) \
    : "r"((a)[0]), "r"((a)[1]), "r"((a)[2]), "r"((a)[3]), "r"(b0), "r"(b1))

#define MOVMAT(d, s) \
  asm volatile("movmatrix.sync.aligned.m8n8.trans.b16 %0, %1;" : "=r"(d) : "r"(s))

__device__ __forceinline__ float warp_sum(float v) {
#pragma unroll
  for (int o = 16; o > 0; o >>= 1) v += __shfl_xor_sync(0xffffffffu, v, o);
  return v;
}
__device__ __forceinline__ float sigmoidf(float x) {
  return 1.f / (1.f + __expf(-x));
}
__device__ __forceinline__ unsigned pack2h(float a, float b) {
  __half2 t = __floats2half2_rn(a, b);
  return *(unsigned*)&t;
}

// ---------------- K_prew: W -> [ch][k] fp16, 6 weights ----------------------
__global__ __launch_bounds__(256) void k_prew(
    const float* __restrict__ Wga, const float* __restrict__ Wpa,
    const float* __restrict__ Wgb, const float* __restrict__ Wpb,
    const float* __restrict__ Wgo, const float* __restrict__ Wpo) {
  const float* srcs[6] = {Wga, Wpa, Wgb, Wpb, Wgo, Wpo};
  const float* W = srcs[blockIdx.y];
  int t = threadIdx.x;
  int ch = blockIdx.x * 16 + (t >> 4);
  int k0 = (t & 15) * 8;
  uint32_t r[4];
#pragma unroll
  for (int q = 0; q < 4; q++) {
    float v0 = W[(k0 + 2 * q) * CDIM + ch];
    float v1 = W[(k0 + 2 * q + 1) * CDIM + ch];
    r[q] = pack2h(v0, v1);
  }
  size_t off = (size_t)blockIdx.y * (CDIM * CDIM) + (size_t)ch * CDIM + k0;
  *(uint4*)(d_w16 + off) = make_uint4(r[0], r[1], r[2], r[3]);
}

// ---------------- K1: fused LN + 5-way projection (unchanged) ---------------
#define APITCH 256
#define SA_BYTES (64 * APITCH)      // 16 KB per A array
#define WPITCH 48                   // 32B data + 16B pad
#define SW_ARR (128 * WPITCH)       // 6144 B per W array chunk
#define SW_BUF (2 * SW_ARR)         // 12288 B per buffer
#define PROJ_SMEM (2 * SA_BYTES + 3 * SW_BUF)   // 69632 B

__device__ __forceinline__ void proj_issue_chunk(int ph, int t, uint32_t sW) {
  int s = ph >> 3, e = ph & 7;
  int arr = t >> 7;           // 0: gate weight, 1: proj weight
  int ch = t & 127;
  if (s < 2 || arr == 0) {
    int widx = s * 2 + arr;   // s=2,arr=0 -> Wgo
    const char* g = (const char*)(d_w16 + (size_t)widx * (CDIM * CDIM) +
                                  (size_t)ch * CDIM + e * 16);
    uint32_t d = sW + (ph % 3) * SW_BUF + arr * SW_ARR + ch * WPITCH;
    CP_ASYNC16(d, g);
    CP_ASYNC16(d + 16, g + 16);
  }
  CP_COMMIT();
}

__global__ __launch_bounds__(256, 2) void k_projmma(
    const float* __restrict__ z, const int* __restrict__ mask,
    const float* __restrict__ lnw, const float* __restrict__ lnb) {
  extern __shared__ char smem[];
  const uint32_t sbase = smem_u32(smem);
  const uint32_t sAhi = sbase, sW = sbase + 2 * SA_BYTES;
  const int n0 = blockIdx.x * 64;
  const int t = threadIdx.x, l = t & 31, w = t >> 5;

  proj_issue_chunk(0, t, sW);
  proj_issue_chunk(1, t, sW);

  {
    float4 wv = *(const float4*)(lnw + l * 4);
    float4 bv = *(const float4*)(lnb + l * 4);
#pragma unroll 4
    for (int it = 0; it < 8; it++) {
      int r = w + it * 8;
      float4 v = *(const float4*)(z + (size_t)(n0 + r) * CDIM + l * 4);
      float mu = warp_sum(v.x + v.y + v.z + v.w) * (1.f / CDIM);
      float dx = v.x - mu, dy = v.y - mu, dz = v.z - mu, dw = v.w - mu;
      float var = warp_sum(dx * dx + dy * dy + dz * dz + dw * dw) * (1.f / CDIM);
      float rstd = rsqrtf(var + EPSV);
      float o0 = dx * rstd * wv.x + bv.x, o1 = dy * rstd * wv.y + bv.y;
      float o2 = dz * rstd * wv.z + bv.z, o3 = dw * rstd * wv.w + bv.w;
      float h0 = __half2float(__float2half_rn(o0));
      float h1 = __half2float(__float2half_rn(o1));
      float h2 = __half2float(__float2half_rn(o2));
      float h3 = __half2float(__float2half_rn(o3));
      uint32_t off = r * APITCH + (((l >> 1) ^ (r & 7)) * 16) + (l & 1) * 8;
      *(uint2*)(smem + off) = make_uint2(pack2h(h0, h1), pack2h(h2, h3));
      *(uint2*)(smem + SA_BYTES + off) =
          make_uint2(pack2h(o0 - h0, o1 - h1), pack2h(o2 - h2, o3 - h3));
    }
  }
  __syncthreads();

  const int a_r = l & 15, a_c = l >> 4;
  const int b_r = (l & 7) + ((l >> 4) << 3), b_c = (l >> 3) & 1;
  const int wm = w & 1, wn = w >> 1;

  float mk[2][2];
#pragma unroll
  for (int mt = 0; mt < 2; mt++)
#pragma unroll
    for (int h = 0; h < 2; h++)
      mk[mt][h] = (float)mask[n0 + wm * 32 + mt * 16 + (l >> 2) + 8 * h];

  float accg[2][4][4], accp[2][4][4];

  for (int ph = 0; ph < 24; ph++) {
    const int s = ph >> 3, e = ph & 7;
    if (ph + 2 < 24) proj_issue_chunk(ph + 2, t, sW);
    if (ph < 22) { CP_WAIT(2); } else if (ph == 22) { CP_WAIT(1); } else { CP_WAIT(0); }
    __syncthreads();

    if (e == 0) {
#pragma unroll
      for (int mt = 0; mt < 2; mt++)
#pragma unroll
        for (int nt = 0; nt < 4; nt++)
#pragma unroll
          for (int q = 0; q < 4; q++) { accg[mt][nt][q] = 0.f; accp[mt][nt][q] = 0.f; }
    }

    const uint32_t wb = sW + (ph % 3) * SW_BUF;
    uint32_t ah[2][4], al[2][4];
#pragma unroll
    for (int mt = 0; mt < 2; mt++) {
      int row = wm * 32 + mt * 16 + a_r;
      uint32_t addr = sAhi + row * APITCH + (((e * 2 + a_c) ^ (row & 7)) * 16);
      LDSM_X4(ah[mt][0], ah[mt][1], ah[mt][2], ah[mt][3], addr);
      if (s < 2)
        LDSM_X4(al[mt][0], al[mt][1], al[mt][2], al[mt][3], addr + SA_BYTES);
    }
#pragma unroll
    for (int gm = 0; gm < 2; gm++) {
      if (s == 2 && gm == 1) break;
      uint32_t bh[2][4];
      const uint32_t Bh = wb + gm * SW_ARR;
#pragma unroll
      for (int np = 0; np < 2; np++) {
        uint32_t caddr = (uint32_t)(wn * 32 + np * 16 + b_r) * WPITCH + b_c * 16;
        LDSM_X4(bh[np][0], bh[np][1], bh[np][2], bh[np][3], Bh + caddr);
      }
#pragma unroll
      for (int mt = 0; mt < 2; mt++) {
#pragma unroll
        for (int nt = 0; nt < 4; nt++) {
          uint32_t h0 = (nt & 1) ? bh[nt >> 1][2] : bh[nt >> 1][0];
          uint32_t h1 = (nt & 1) ? bh[nt >> 1][3] : bh[nt >> 1][1];
          float* acc = gm ? accp[mt][nt] : accg[mt][nt];
          MMAH16816(acc, ah[mt], h0, h1);
          if (gm == 1) MMAH16816(acc, al[mt], h0, h1);
        }
      }
    }

    if (e == 7) {
      if (s < 2) {
        __half* dst16 = s ? d_b16 : d_a16;
#pragma unroll
        for (int mt = 0; mt < 2; mt++) {
#pragma unroll
          for (int h = 0; h < 2; h++) {
            int nb = n0 + wm * 32 + mt * 16 + 8 * h + 2 * (l & 3);
#pragma unroll
            for (int nt = 0; nt < 4; nt++) {
              float v0 = sigmoidf(accg[mt][nt][2 * h]) * accp[mt][nt][2 * h] * mk[mt][h];
              float v1 = sigmoidf(accg[mt][nt][2 * h + 1]) * accp[mt][nt][2 * h + 1] * mk[mt][h];
              uint32_t hreg = pack2h(v0, v1);
              uint32_t ht;
              MOVMAT(ht, hreg);
              size_t chrow = (size_t)(wn * 32 + nt * 8 + (l >> 2));
              *(uint32_t*)(dst16 + chrow * NROWS + nb) = ht;
            }
          }
        }
      } else {
#pragma unroll
        for (int mt = 0; mt < 2; mt++) {
#pragma unroll
          for (int h = 0; h < 2; h++) {
            int n = n0 + wm * 32 + mt * 16 + (l >> 2) + 8 * h;
            float* dst = d_g + (size_t)n * CDIM + wn * 32 + 2 * (l & 3);
#pragma unroll
            for (int nt = 0; nt < 4; nt++) {
              float2 o = make_float2(sigmoidf(accg[mt][nt][2 * h]),
                                     sigmoidf(accg[mt][nt][2 * h + 1]));
              *(float2*)(dst + nt * 8) = o;
            }
          }
        }
      }
    }
    __syncthreads();
  }
}

// ---------------- K2: einsum v2 — 64x128 tile, 3 CTAs/SM --------------------
#define EROWB 80
#define E_AROWS 64
#define STAGEB ((E_AROWS + 128) * EROWB)   // 15360 per stage
#define EIN_SMEM (3 * STAGEB)              // 46080

__global__ __launch_bounds__(256, 3) void k_einsum_mma() {
  extern __shared__ char smem[];
  const uint32_t sbase = smem_u32(smem);
  const int c = blockIdx.z;
  const int i0 = blockIdx.x * 64, j0 = blockIdx.y * 128;
  const int tid = threadIdx.x;
  const size_t coff = (size_t)c * NROWS;

  // loaders: threads 0-63 -> a rows, 64-191 -> b rows, 192-255 idle
  const bool loads = tid < 192;
  const __half* lsrc = (tid < 64)
      ? d_a16 + coff + (size_t)(i0 + tid) * LDIM
      : d_b16 + coff + (size_t)(j0 + (tid - 64)) * LDIM;
  const uint32_t lsmem = sbase + tid * EROWB;

#define ISSUE_LOAD(stage, kc) do { \
    if (loads) { \
      const char* g0 = (const char*)(lsrc + (kc)); \
      uint32_t s0 = lsmem + (stage) * STAGEB; \
      CP_ASYNC16(s0,      g0);      CP_ASYNC16(s0 + 16, g0 + 16); \
      CP_ASYNC16(s0 + 32, g0 + 32); CP_ASYNC16(s0 + 48, g0 + 48); \
    } \
    CP_COMMIT(); \
  } while (0)

  const int w = tid >> 5, l = tid & 31;
  const int wm = w & 1, wn = w >> 1;    // 2(i) x 4(j) warps, warp tile 32x32
  const int a_r = l & 15, a_c = l >> 4;
  const int b_r = (l & 7) + ((l >> 4) << 3);
  const int b_c = (l >> 3) & 1;

  float acc[2][4][4];
#pragma unroll
  for (int mt = 0; mt < 2; mt++)
#pragma unroll
    for (int nt = 0; nt < 4; nt++)
#pragma unroll
      for (int q = 0; q < 4; q++) acc[mt][nt][q] = 0.f;

  ISSUE_LOAD(0, 0);
  ISSUE_LOAD(1, 32);

  for (int ci = 0; ci < 16; ci++) {
    const int stage = ci % 3;
    if (ci < 14) { ISSUE_LOAD((ci + 2) % 3, (ci + 2) * 32); CP_WAIT(2); }
    else if (ci == 14) { CP_WAIT(1); } else { CP_WAIT(0); }
    __syncthreads();

    const uint32_t bufbase = sbase + stage * STAGEB;
#pragma unroll
    for (int ks = 0; ks < 2; ks++) {
      const uint32_t kof = ks * 32 + a_c * 16;
      const uint32_t kofb = ks * 32 + b_c * 16;
      uint32_t ah[2][4], bh[2][4];
#pragma unroll
      for (int mt = 0; mt < 2; mt++) {
        uint32_t addr = bufbase + (uint32_t)(wm * 32 + mt * 16 + a_r) * EROWB + kof;
        LDSM_X4(ah[mt][0], ah[mt][1], ah[mt][2], ah[mt][3], addr);
      }
#pragma unroll
      for (int np = 0; np < 2; np++) {
        uint32_t addr = bufbase + (uint32_t)(E_AROWS + wn * 32 + np * 16 + b_r) * EROWB + kofb;
        LDSM_X4(bh[np][0], bh[np][1], bh[np][2], bh[np][3], addr);
      }
#pragma unroll
      for (int mt = 0; mt < 2; mt++)
#pragma unroll
        for (int nt = 0; nt < 4; nt++) {
          uint32_t b0 = (nt & 1) ? bh[nt >> 1][2] : bh[nt >> 1][0];
          uint32_t b1 = (nt & 1) ? bh[nt >> 1][3] : bh[nt >> 1][1];
          MMAH16816(acc[mt][nt], ah[mt], b0, b1);
        }
    }
    __syncthreads();
  }

  float* mbase = d_mt + coff;
#pragma unroll
  for (int mt = 0; mt < 2; mt++) {
#pragma unroll
    for (int h = 0; h < 2; h++) {
      int row = i0 + wm * 32 + mt * 16 + (l >> 2) + h * 8;
      float* rp = mbase + (size_t)row * LDIM + j0 + wn * 32 + (l & 3) * 2;
#pragma unroll
      for (int nt = 0; nt < 4; nt++) {
        float2 v = make_float2(acc[mt][nt][h * 2], acc[mt][nt][h * 2 + 1]);
        *(float2*)(rp + nt * 8) = v;
      }
    }
  }
#undef ISSUE_LOAD
}

// ---------------- K3: LN(m) + @W_proj_out — A overlaid in msf, 3 CTAs/SM ----
// Region 0 (33024 B): msf fp32 rows pitch 129 floats; after LN consumed,
// A fp16 tiles overlaid at base 256, pitch 512 (hi +0, lo +256).
// Overlap-safe: A[jj] bottom 256+512jj >= 516jj (msf row jj start) for all jj,
// LN processed in DESCENDING batches with read->sync->write per batch.
#define MSW 129
#define KO_REGION 33024
#define KO_AB 256                        // A base within region
#define KO_SW KO_REGION                  // W base
#define KO_SW_BYTES (128 * 256)          // 32768
#define KO_SMEM (KO_REGION + KO_SW_BYTES) // 65792

__global__ __launch_bounds__(256, 3) void k_outmma(
    const float* __restrict__ lnw, const float* __restrict__ lnb,
    const int* __restrict__ mask, float* __restrict__ out) {
  extern __shared__ char smem[];
  const uint32_t sbase = smem_u32(smem);
  float* msf = (float*)smem;
  const int i = blockIdx.y;
  const int j0 = blockIdx.x * 64;
  const int t = threadIdx.x, l = t & 31, w = t >> 5;

  // stage Wpo fp16 (slot 5) with XOR swizzle
  {
    int row = t >> 1, half = t & 1;
    const __half* sh = d_w16 + 5 * (CDIM * CDIM) + (size_t)row * CDIM;
    uint32_t dbase = sbase + KO_SW + (uint32_t)row * 256;
#pragma unroll
    for (int q = 0; q < 8; q++) {
      int k16 = half * 8 + q;
      CP_ASYNC16(dbase + ((k16 ^ (row & 7)) * 16), (const char*)(sh + k16 * 8));
    }
    CP_COMMIT();
  }

  // gather m[c][i][j0..j0+63] -> msf[jj][c]
#pragma unroll
  for (int q = 0; q < 16; q++) {
    int c = w + 8 * q;
    const float* src = d_mt + (size_t)c * NROWS + (size_t)i * LDIM + j0;
    msf[l * MSW + c] = src[l];
    msf[(l + 32) * MSW + c] = src[l + 32];
  }
  __syncthreads();

  // LN over c, descending batches; write fp16 hi/lo A tiles into region
  {
    float4 wv = *(const float4*)(lnw + l * 4);
    float4 bv = *(const float4*)(lnb + l * 4);
#pragma unroll
    for (int it = 7; it >= 0; it--) {
      int jj = w + it * 8;
      const float* rowp = msf + jj * MSW + l * 4;
      float x0 = rowp[0], x1 = rowp[1], x2 = rowp[2], x3 = rowp[3];
      float mu = warp_sum(x0 + x1 + x2 + x3) * (1.f / CDIM);
      float d0 = x0 - mu, d1 = x1 - mu, d2 = x2 - mu, d3 = x3 - mu;
      float var = warp_sum(d0 * d0 + d1 * d1 + d2 * d2 + d3 * d3) * (1.f / CDIM);
      float rstd = rsqrtf(var + EPSV);
      float o0 = d0 * rstd * wv.x + bv.x, o1 = d1 * rstd * wv.y + bv.y;
      float o2 = d2 * rstd * wv.z + bv.z, o3 = d3 * rstd * wv.w + bv.w;
      float h0 = __half2float(__float2half_rn(o0));
      float h1 = __half2float(__float2half_rn(o1));
      float h2 = __half2float(__float2half_rn(o2));
      float h3 = __half2float(__float2half_rn(o3));
      __syncthreads();   // all reads of this batch done before overlaid writes
      uint32_t off = KO_AB + jj * 512 + (((l >> 1) ^ (jj & 7)) * 16) + (l & 1) * 8;
      *(uint2*)(smem + off) = make_uint2(pack2h(h0, h1), pack2h(h2, h3));
      *(uint2*)(smem + off + 256) =
          make_uint2(pack2h(o0 - h0, o1 - h1), pack2h(o2 - h2, o3 - h3));
    }
  }
  CP_WAIT(0);
  __syncthreads();

  // MMA: M=64 (jj), N=128 (out ch), K=128 (c); 2(M)x4(N) warps, 2 terms
  const int a_r = l & 15, a_c = l >> 4;
  const int b_r = (l & 7) + ((l >> 4) << 3), b_c = (l >> 3) & 1;
  const int wm = w & 1, wn = w >> 1;

  float acc[2][4][4];
#pragma unroll
  for (int mt = 0; mt < 2; mt++)
#pragma unroll
    for (int nt = 0; nt < 4; nt++)
#pragma unroll
      for (int q = 0; q < 4; q++) acc[mt][nt][q] = 0.f;

#pragma unroll
  for (int e = 0; e < 8; e++) {
    uint32_t ah[2][4], al[2][4], bh[2][4];
#pragma unroll
    for (int mt = 0; mt < 2; mt++) {
      int row = wm * 32 + mt * 16 + a_r;
      uint32_t addr = sbase + KO_AB + row * 512 + (((e * 2 + a_c) ^ (row & 7)) * 16);
      LDSM_X4(ah[mt][0], ah[mt][1], ah[mt][2], ah[mt][3], addr);
      LDSM_X4(al[mt][0], al[mt][1], al[mt][2], al[mt][3], addr + 256);
    }
#pragma unroll
    for (int np = 0; np < 2; np++) {
      int row = wn * 32 + np * 16 + b_r;
      uint32_t addr = sbase + KO_SW + row * 256 + (((e * 2 + b_c) ^ (row & 7)) * 16);
      LDSM_X4(bh[np][0], bh[np][1], bh[np][2], bh[np][3], addr);
    }
#pragma unroll
    for (int mt = 0; mt < 2; mt++)
#pragma unroll
      for (int nt = 0; nt < 4; nt++) {
        uint32_t h0 = (nt & 1) ? bh[nt >> 1][2] : bh[nt >> 1][0];
        uint32_t h1 = (nt & 1) ? bh[nt >> 1][3] : bh[nt >> 1][1];
        MMAH16816(acc[mt][nt], ah[mt], h0, h1);
        MMAH16816(acc[mt][nt], al[mt], h0, h1);
      }
  }

  // epilogue: out[n][ch] = acc * g * mask
#pragma unroll
  for (int mt = 0; mt < 2; mt++) {
#pragma unroll
    for (int h = 0; h < 2; h++) {
      int jj = wm * 32 + mt * 16 + (l >> 2) + 8 * h;
      size_t n = (size_t)i * LDIM + j0 + jj;
      float mkv = (float)mask[n];
      float* dst = out + n * CDIM + wn * 32 + 2 * (l & 3);
      const float* gsrc = d_g + n * CDIM + wn * 32 + 2 * (l & 3);
#pragma unroll
      for (int nt = 0; nt < 4; nt++) {
        float2 g2 = *(const float2*)(gsrc + nt * 8);
        float2 o = make_float2(acc[mt][nt][2 * h] * g2.x * mkv,
                               acc[mt][nt][2 * h + 1] * g2.y * mkv);
        *(float2*)(dst + nt * 8) = o;
      }
    }
  }
}

// ---------------- launch ----------------------------------------------------
extern "C" void kernel_launch(void* const* d_in, const int* in_sizes, int n_in,
                              void* d_out, int out_size) {
  const float* z        = (const float*)d_in[0];
  const int*   mask     = (const int*)  d_in[1];
  const float* ln_in_w  = (const float*)d_in[2];
  const float* ln_in_b  = (const float*)d_in[3];
  const float* ln_out_w = (const float*)d_in[4];
  const float* ln_out_b = (const float*)d_in[5];
  const float* Wpa = (const float*)d_in[6];
  const float* Wga = (const float*)d_in[7];
  const float* Wpb = (const float*)d_in[8];
  const float* Wgb = (const float*)d_in[9];
  const float* Wgo = (const float*)d_in[10];
  const float* Wpo = (const float*)d_in[11];
  float* out = (float*)d_out;

  cudaFuncSetAttribute(k_projmma, cudaFuncAttributeMaxDynamicSharedMemorySize, PROJ_SMEM);
  cudaFuncSetAttribute(k_einsum_mma, cudaFuncAttributeMaxDynamicSharedMemorySize, EIN_SMEM);
  cudaFuncSetAttribute(k_outmma, cudaFuncAttributeMaxDynamicSharedMemorySize, KO_SMEM);

  k_prew<<<dim3(8, 6), 256>>>(Wga, Wpa, Wgb, Wpb, Wgo, Wpo);
  k_projmma<<<NROWS / 64, 256, PROJ_SMEM>>>(z, mask, ln_in_w, ln_in_b);
  dim3 g2(LDIM / 64, LDIM / 128, CDIM);
  k_einsum_mma<<<g2, 256, EIN_SMEM>>>();
  dim3 g3(LDIM / 64, LDIM);
  k_outmma<<<g3, 256, KO_SMEM>>>(ln_out_w, ln_out_b, mask, out);
}

// round 17
// speedup vs baseline: 1.0762x; 1.0762x over previous
#include <cuda_runtime.h>
#include <cuda_bf16.h>
#include <cuda_fp16.h>
#include <cstdint>

#define LDIM 512
#define CDIM 128
#define NROWS (LDIM * LDIM)   // 262144 pair rows
#define EPSV 1e-5f

// ---------------- scratch (static device memory; no runtime allocation) ----
__device__ float d_g  [(size_t)NROWS * CDIM];      // sigmoid(zln @ W_gate_out), [n][c]
__device__ __half d_a16[(size_t)CDIM * NROWS];     // a fp16: [c][i][k]
__device__ __half d_b16[(size_t)CDIM * NROWS];     // b fp16: [c][j][k]
__device__ float d_mt [(size_t)CDIM * NROWS];      // einsum result: [c][i][j]
// pre-transposed weights [w][ch][k] fp16; slots: Wga,Wpa,Wgb,Wpb,Wgo,Wpo
__device__ __half d_w16[6 * CDIM * CDIM];

// ---------------- arch-generic PTX helpers (plain sm_103 target!) ----------
__device__ __forceinline__ uint32_t smem_u32(const void* p) {
  uint32_t a;
  asm("{ .reg .u64 t; cvta.to.shared.u64 t, %1; cvt.u32.u64 %0, t; }" : "=r"(a) : "l"(p));
  return a;
}
#define CP_ASYNC16(s, g) \
  asm volatile("cp.async.cg.shared.global [%0], [%1], 16;" :: "r"(s), "l"(g) : "memory")
#define CP_COMMIT() asm volatile("cp.async.commit_group;" ::: "memory")
#define CP_WAIT(n)  asm volatile("cp.async.wait_group %0;" :: "n"(n) : "memory")

#define LDSM_X4(r0, r1, r2, r3, addr) \
  asm volatile("ldmatrix.sync.aligned.m8n8.x4.shared.b16 {%0,%1,%2,%3}, [%4];" \
    : "=r"(r0), "=r"(r1), "=r"(r2), "=r"(r3) : "r"(addr))

#define MMAH16816(d, a, b0, b1) \
  asm volatile("mma.sync.aligned.m16n8k16.row.col.f32.f16.f16.f32 " \
    "{%0,%1,%2,%3}, {%4,%5,%6,%7}, {%8,%9}, {%0,%1,%2,%3};" \
    : "+f"((d)[0]), "+f"((d)[1]), "+f"((d)[2]), "+f"((d)[3]) \
    : "r"((a)[0]), "r"((a)[1]), "r"((a)[2]), "r"((a)[3]), "r"(b0), "r"(b1))

#define MOVMAT(d, s) \
  asm volatile("movmatrix.sync.aligned.m8n8.trans.b16 %0, %1;" : "=r"(d) : "r"(s))

__device__ __forceinline__ float warp_sum(float v) {
#pragma unroll
  for (int o = 16; o > 0; o >>= 1) v += __shfl_xor_sync(0xffffffffu, v, o);
  return v;
}
__device__ __forceinline__ float sigmoidf(float x) {
  return 1.f / (1.f + __expf(-x));
}
__device__ __forceinline__ unsigned pack2h(float a, float b) {
  __half2 t = __floats2half2_rn(a, b);
  return *(unsigned*)&t;
}

// ---------------- K_prew: W -> [ch][k] fp16, 6 weights ----------------------
__global__ __launch_bounds__(256) void k_prew(
    const float* __restrict__ Wga, const float* __restrict__ Wpa,
    const float* __restrict__ Wgb, const float* __restrict__ Wpb,
    const float* __restrict__ Wgo, const float* __restrict__ Wpo) {
  const float* srcs[6] = {Wga, Wpa, Wgb, Wpb, Wgo, Wpo};
  const float* W = srcs[blockIdx.y];
  int t = threadIdx.x;
  int ch = blockIdx.x * 16 + (t >> 4);
  int k0 = (t & 15) * 8;
  uint32_t r[4];
#pragma unroll
  for (int q = 0; q < 4; q++) {
    float v0 = W[(k0 + 2 * q) * CDIM + ch];
    float v1 = W[(k0 + 2 * q + 1) * CDIM + ch];
    r[q] = pack2h(v0, v1);
  }
  size_t off = (size_t)blockIdx.y * (CDIM * CDIM) + (size_t)ch * CDIM + k0;
  *(uint4*)(d_w16 + off) = make_uint4(r[0], r[1], r[2], r[3]);
}

// ---------------- K1: fused LN + 5-way projection (unchanged) ---------------
#define APITCH 256
#define SA_BYTES (64 * APITCH)      // 16 KB per A array
#define WPITCH 48                   // 32B data + 16B pad
#define SW_ARR (128 * WPITCH)       // 6144 B per W array chunk
#define SW_BUF (2 * SW_ARR)         // 12288 B per buffer
#define PROJ_SMEM (2 * SA_BYTES + 3 * SW_BUF)   // 69632 B

__device__ __forceinline__ void proj_issue_chunk(int ph, int t, uint32_t sW) {
  int s = ph >> 3, e = ph & 7;
  int arr = t >> 7;           // 0: gate weight, 1: proj weight
  int ch = t & 127;
  if (s < 2 || arr == 0) {
    int widx = s * 2 + arr;   // s=2,arr=0 -> Wgo
    const char* g = (const char*)(d_w16 + (size_t)widx * (CDIM * CDIM) +
                                  (size_t)ch * CDIM + e * 16);
    uint32_t d = sW + (ph % 3) * SW_BUF + arr * SW_ARR + ch * WPITCH;
    CP_ASYNC16(d, g);
    CP_ASYNC16(d + 16, g + 16);
  }
  CP_COMMIT();
}

__global__ __launch_bounds__(256, 2) void k_projmma(
    const float* __restrict__ z, const int* __restrict__ mask,
    const float* __restrict__ lnw, const float* __restrict__ lnb) {
  extern __shared__ char smem[];
  const uint32_t sbase = smem_u32(smem);
  const uint32_t sAhi = sbase, sW = sbase + 2 * SA_BYTES;
  const int n0 = blockIdx.x * 64;
  const int t = threadIdx.x, l = t & 31, w = t >> 5;

  proj_issue_chunk(0, t, sW);
  proj_issue_chunk(1, t, sW);

  {
    float4 wv = *(const float4*)(lnw + l * 4);
    float4 bv = *(const float4*)(lnb + l * 4);
#pragma unroll 4
    for (int it = 0; it < 8; it++) {
      int r = w + it * 8;
      float4 v = *(const float4*)(z + (size_t)(n0 + r) * CDIM + l * 4);
      float mu = warp_sum(v.x + v.y + v.z + v.w) * (1.f / CDIM);
      float dx = v.x - mu, dy = v.y - mu, dz = v.z - mu, dw = v.w - mu;
      float var = warp_sum(dx * dx + dy * dy + dz * dz + dw * dw) * (1.f / CDIM);
      float rstd = rsqrtf(var + EPSV);
      float o0 = dx * rstd * wv.x + bv.x, o1 = dy * rstd * wv.y + bv.y;
      float o2 = dz * rstd * wv.z + bv.z, o3 = dw * rstd * wv.w + bv.w;
      float h0 = __half2float(__float2half_rn(o0));
      float h1 = __half2float(__float2half_rn(o1));
      float h2 = __half2float(__float2half_rn(o2));
      float h3 = __half2float(__float2half_rn(o3));
      uint32_t off = r * APITCH + (((l >> 1) ^ (r & 7)) * 16) + (l & 1) * 8;
      *(uint2*)(smem + off) = make_uint2(pack2h(h0, h1), pack2h(h2, h3));
      *(uint2*)(smem + SA_BYTES + off) =
          make_uint2(pack2h(o0 - h0, o1 - h1), pack2h(o2 - h2, o3 - h3));
    }
  }
  __syncthreads();

  const int a_r = l & 15, a_c = l >> 4;
  const int b_r = (l & 7) + ((l >> 4) << 3), b_c = (l >> 3) & 1;
  const int wm = w & 1, wn = w >> 1;

  float mk[2][2];
#pragma unroll
  for (int mt = 0; mt < 2; mt++)
#pragma unroll
    for (int h = 0; h < 2; h++)
      mk[mt][h] = (float)mask[n0 + wm * 32 + mt * 16 + (l >> 2) + 8 * h];

  float accg[2][4][4], accp[2][4][4];

  for (int ph = 0; ph < 24; ph++) {
    const int s = ph >> 3, e = ph & 7;
    if (ph + 2 < 24) proj_issue_chunk(ph + 2, t, sW);
    if (ph < 22) { CP_WAIT(2); } else if (ph == 22) { CP_WAIT(1); } else { CP_WAIT(0); }
    __syncthreads();

    if (e == 0) {
#pragma unroll
      for (int mt = 0; mt < 2; mt++)
#pragma unroll
        for (int nt = 0; nt < 4; nt++)
#pragma unroll
          for (int q = 0; q < 4; q++) { accg[mt][nt][q] = 0.f; accp[mt][nt][q] = 0.f; }
    }

    const uint32_t wb = sW + (ph % 3) * SW_BUF;
    uint32_t ah[2][4], al[2][4];
#pragma unroll
    for (int mt = 0; mt < 2; mt++) {
      int row = wm * 32 + mt * 16 + a_r;
      uint32_t addr = sAhi + row * APITCH + (((e * 2 + a_c) ^ (row & 7)) * 16);
      LDSM_X4(ah[mt][0], ah[mt][1], ah[mt][2], ah[mt][3], addr);
      if (s < 2)
        LDSM_X4(al[mt][0], al[mt][1], al[mt][2], al[mt][3], addr + SA_BYTES);
    }
#pragma unroll
    for (int gm = 0; gm < 2; gm++) {
      if (s == 2 && gm == 1) break;
      uint32_t bh[2][4];
      const uint32_t Bh = wb + gm * SW_ARR;
#pragma unroll
      for (int np = 0; np < 2; np++) {
        uint32_t caddr = (uint32_t)(wn * 32 + np * 16 + b_r) * WPITCH + b_c * 16;
        LDSM_X4(bh[np][0], bh[np][1], bh[np][2], bh[np][3], Bh + caddr);
      }
#pragma unroll
      for (int mt = 0; mt < 2; mt++) {
#pragma unroll
        for (int nt = 0; nt < 4; nt++) {
          uint32_t h0 = (nt & 1) ? bh[nt >> 1][2] : bh[nt >> 1][0];
          uint32_t h1 = (nt & 1) ? bh[nt >> 1][3] : bh[nt >> 1][1];
          float* acc = gm ? accp[mt][nt] : accg[mt][nt];
          MMAH16816(acc, ah[mt], h0, h1);
          if (gm == 1) MMAH16816(acc, al[mt], h0, h1);
        }
      }
    }

    if (e == 7) {
      if (s < 2) {
        __half* dst16 = s ? d_b16 : d_a16;
#pragma unroll
        for (int mt = 0; mt < 2; mt++) {
#pragma unroll
          for (int h = 0; h < 2; h++) {
            int nb = n0 + wm * 32 + mt * 16 + 8 * h + 2 * (l & 3);
#pragma unroll
            for (int nt = 0; nt < 4; nt++) {
              float v0 = sigmoidf(accg[mt][nt][2 * h]) * accp[mt][nt][2 * h] * mk[mt][h];
              float v1 = sigmoidf(accg[mt][nt][2 * h + 1]) * accp[mt][nt][2 * h + 1] * mk[mt][h];
              uint32_t hreg = pack2h(v0, v1);
              uint32_t ht;
              MOVMAT(ht, hreg);
              size_t chrow = (size_t)(wn * 32 + nt * 8 + (l >> 2));
              *(uint32_t*)(dst16 + chrow * NROWS + nb) = ht;
            }
          }
        }
      } else {
#pragma unroll
        for (int mt = 0; mt < 2; mt++) {
#pragma unroll
          for (int h = 0; h < 2; h++) {
            int n = n0 + wm * 32 + mt * 16 + (l >> 2) + 8 * h;
            float* dst = d_g + (size_t)n * CDIM + wn * 32 + 2 * (l & 3);
#pragma unroll
            for (int nt = 0; nt < 4; nt++) {
              float2 o = make_float2(sigmoidf(accg[mt][nt][2 * h]),
                                     sigmoidf(accg[mt][nt][2 * h + 1]));
              *(float2*)(dst + nt * 8) = o;
            }
          }
        }
      }
    }
    __syncthreads();
  }
}

// ---------------- K2: channel-batched einsum, fp16 1-term, 3-stage (R13) ----
#define EROWB 80
#define ARRB (128 * EROWB)          // 10240 per array
#define STAGEB (2 * ARRB)           // 20480 per stage (a tile + b tile)
#define EIN_SMEM (3 * STAGEB)       // 61440

__global__ __launch_bounds__(256, 2) void k_einsum_mma() {
  extern __shared__ char smem[];
  const uint32_t sbase = smem_u32(smem);
  const int c = blockIdx.z;
  const int i0 = blockIdx.x * 128, j0 = blockIdx.y * 128;
  const int tid = threadIdx.x;
  const size_t coff = (size_t)c * NROWS;

  const int larr = tid >> 7;            // 0: a tile (i rows), 1: b tile (j rows)
  const int lrow = tid & 127;
  const __half* lsrc = (larr ? d_b16 + coff + (size_t)(j0 + lrow) * LDIM
                             : d_a16 + coff + (size_t)(i0 + lrow) * LDIM);
  const uint32_t lsmem = sbase + larr * ARRB + lrow * EROWB;

#define ISSUE_LOAD(stage, kc) do { \
    const char* g0 = (const char*)(lsrc + (kc)); \
    uint32_t s0 = lsmem + (stage) * STAGEB; \
    CP_ASYNC16(s0,      g0);      CP_ASYNC16(s0 + 16, g0 + 16); \
    CP_ASYNC16(s0 + 32, g0 + 32); CP_ASYNC16(s0 + 48, g0 + 48); \
    CP_COMMIT(); \
  } while (0)

  const int w = tid >> 5, l = tid & 31;
  const int wm = w & 1, wn = w >> 1;
  const int a_r = l & 15, a_c = l >> 4;
  const int b_r = (l & 7) + ((l >> 4) << 3);
  const int b_c = (l >> 3) & 1;

  float acc[4][4][4];
#pragma unroll
  for (int mt = 0; mt < 4; mt++)
#pragma unroll
    for (int nt = 0; nt < 4; nt++)
#pragma unroll
      for (int q = 0; q < 4; q++) acc[mt][nt][q] = 0.f;

  ISSUE_LOAD(0, 0);
  ISSUE_LOAD(1, 32);

  for (int ci = 0; ci < 16; ci++) {
    const int stage = ci % 3;
    if (ci < 14) { ISSUE_LOAD((ci + 2) % 3, (ci + 2) * 32); CP_WAIT(2); }
    else if (ci == 14) { CP_WAIT(1); } else { CP_WAIT(0); }
    __syncthreads();

    const uint32_t bufbase = sbase + stage * STAGEB;
#pragma unroll
    for (int ks = 0; ks < 2; ks++) {
      const uint32_t kof = ks * 32 + a_c * 16;
      const uint32_t kofb = ks * 32 + b_c * 16;
      uint32_t ah[4][4], bh[2][4];
#pragma unroll
      for (int mt = 0; mt < 4; mt++) {
        uint32_t addr = bufbase + (uint32_t)(wm * 64 + mt * 16 + a_r) * EROWB + kof;
        LDSM_X4(ah[mt][0], ah[mt][1], ah[mt][2], ah[mt][3], addr);
      }
#pragma unroll
      for (int np = 0; np < 2; np++) {
        uint32_t addr = bufbase + ARRB + (uint32_t)(wn * 32 + np * 16 + b_r) * EROWB + kofb;
        LDSM_X4(bh[np][0], bh[np][1], bh[np][2], bh[np][3], addr);
      }
#pragma unroll
      for (int mt = 0; mt < 4; mt++)
#pragma unroll
        for (int nt = 0; nt < 4; nt++) {
          uint32_t b0 = (nt & 1) ? bh[nt >> 1][2] : bh[nt >> 1][0];
          uint32_t b1 = (nt & 1) ? bh[nt >> 1][3] : bh[nt >> 1][1];
          MMAH16816(acc[mt][nt], ah[mt], b0, b1);
        }
    }
    __syncthreads();
  }

  float* mbase = d_mt + coff;
#pragma unroll
  for (int mt = 0; mt < 4; mt++) {
#pragma unroll
    for (int h = 0; h < 2; h++) {
      int row = i0 + wm * 64 + mt * 16 + (l >> 2) + h * 8;
      float* rp = mbase + (size_t)row * LDIM + j0 + wn * 32 + (l & 3) * 2;
#pragma unroll
      for (int nt = 0; nt < 4; nt++) {
        float2 v = make_float2(acc[mt][nt][h * 2], acc[mt][nt][h * 2 + 1]);
        *(float2*)(rp + nt * 8) = v;
      }
    }
  }
#undef ISSUE_LOAD
}

// ---------------- K3: LN(m) + @W_proj_out — A overlaid in msf, 3 CTAs/SM ----
#define MSW 129
#define KO_REGION 33024
#define KO_AB 256                        // A base within region
#define KO_SW KO_REGION                  // W base
#define KO_SW_BYTES (128 * 256)          // 32768
#define KO_SMEM (KO_REGION + KO_SW_BYTES) // 65792

__global__ __launch_bounds__(256, 3) void k_outmma(
    const float* __restrict__ lnw, const float* __restrict__ lnb,
    const int* __restrict__ mask, float* __restrict__ out) {
  extern __shared__ char smem[];
  const uint32_t sbase = smem_u32(smem);
  float* msf = (float*)smem;
  const int i = blockIdx.y;
  const int j0 = blockIdx.x * 64;
  const int t = threadIdx.x, l = t & 31, w = t >> 5;

  // stage Wpo fp16 (slot 5) with XOR swizzle
  {
    int row = t >> 1, half = t & 1;
    const __half* sh = d_w16 + 5 * (CDIM * CDIM) + (size_t)row * CDIM;
    uint32_t dbase = sbase + KO_SW + (uint32_t)row * 256;
#pragma unroll
    for (int q = 0; q < 8; q++) {
      int k16 = half * 8 + q;
      CP_ASYNC16(dbase + ((k16 ^ (row & 7)) * 16), (const char*)(sh + k16 * 8));
    }
    CP_COMMIT();
  }

  // gather m[c][i][j0..j0+63] -> msf[jj][c]
#pragma unroll
  for (int q = 0; q < 16; q++) {
    int c = w + 8 * q;
    const float* src = d_mt + (size_t)c * NROWS + (size_t)i * LDIM + j0;
    msf[l * MSW + c] = src[l];
    msf[(l + 32) * MSW + c] = src[l + 32];
  }
  __syncthreads();

  // LN over c, descending batches; write fp16 hi/lo A tiles into region
  {
    float4 wv = *(const float4*)(lnw + l * 4);
    float4 bv = *(const float4*)(lnb + l * 4);
#pragma unroll
    for (int it = 7; it >= 0; it--) {
      int jj = w + it * 8;
      const float* rowp = msf + jj * MSW + l * 4;
      float x0 = rowp[0], x1 = rowp[1], x2 = rowp[2], x3 = rowp[3];
      float mu = warp_sum(x0 + x1 + x2 + x3) * (1.f / CDIM);
      float d0 = x0 - mu, d1 = x1 - mu, d2 = x2 - mu, d3 = x3 - mu;
      float var = warp_sum(d0 * d0 + d1 * d1 + d2 * d2 + d3 * d3) * (1.f / CDIM);
      float rstd = rsqrtf(var + EPSV);
      float o0 = d0 * rstd * wv.x + bv.x, o1 = d1 * rstd * wv.y + bv.y;
      float o2 = d2 * rstd * wv.z + bv.z, o3 = d3 * rstd * wv.w + bv.w;
      float h0 = __half2float(__float2half_rn(o0));
      float h1 = __half2float(__float2half_rn(o1));
      float h2 = __half2float(__float2half_rn(o2));
      float h3 = __half2float(__float2half_rn(o3));
      __syncthreads();   // all reads of this batch done before overlaid writes
      uint32_t off = KO_AB + jj * 512 + (((l >> 1) ^ (jj & 7)) * 16) + (l & 1) * 8;
      *(uint2*)(smem + off) = make_uint2(pack2h(h0, h1), pack2h(h2, h3));
      *(uint2*)(smem + off + 256) =
          make_uint2(pack2h(o0 - h0, o1 - h1), pack2h(o2 - h2, o3 - h3));
    }
  }
  CP_WAIT(0);
  __syncthreads();

  // MMA: M=64 (jj), N=128 (out ch), K=128 (c); 2(M)x4(N) warps, 2 terms
  const int a_r = l & 15, a_c = l >> 4;
  const int b_r = (l & 7) + ((l >> 4) << 3), b_c = (l >> 3) & 1;
  const int wm = w & 1, wn = w >> 1;

  float acc[2][4][4];
#pragma unroll
  for (int mt = 0; mt < 2; mt++)
#pragma unroll
    for (int nt = 0; nt < 4; nt++)
#pragma unroll
      for (int q = 0; q < 4; q++) acc[mt][nt][q] = 0.f;

#pragma unroll
  for (int e = 0; e < 8; e++) {
    uint32_t ah[2][4], al[2][4], bh[2][4];
#pragma unroll
    for (int mt = 0; mt < 2; mt++) {
      int row = wm * 32 + mt * 16 + a_r;
      uint32_t addr = sbase + KO_AB + row * 512 + (((e * 2 + a_c) ^ (row & 7)) * 16);
      LDSM_X4(ah[mt][0], ah[mt][1], ah[mt][2], ah[mt][3], addr);
      LDSM_X4(al[mt][0], al[mt][1], al[mt][2], al[mt][3], addr + 256);
    }
#pragma unroll
    for (int np = 0; np < 2; np++) {
      int row = wn * 32 + np * 16 + b_r;
      uint32_t addr = sbase + KO_SW + row * 256 + (((e * 2 + b_c) ^ (row & 7)) * 16);
      LDSM_X4(bh[np][0], bh[np][1], bh[np][2], bh[np][3], addr);
    }
#pragma unroll
    for (int mt = 0; mt < 2; mt++)
#pragma unroll
      for (int nt = 0; nt < 4; nt++) {
        uint32_t h0 = (nt & 1) ? bh[nt >> 1][2] : bh[nt >> 1][0];
        uint32_t h1 = (nt & 1) ? bh[nt >> 1][3] : bh[nt >> 1][1];
        MMAH16816(acc[mt][nt], ah[mt], h0, h1);
        MMAH16816(acc[mt][nt], al[mt], h0, h1);
      }
  }

  // epilogue: out[n][ch] = acc * g * mask
#pragma unroll
  for (int mt = 0; mt < 2; mt++) {
#pragma unroll
    for (int h = 0; h < 2; h++) {
      int jj = wm * 32 + mt * 16 + (l >> 2) + 8 * h;
      size_t n = (size_t)i * LDIM + j0 + jj;
      float mkv = (float)mask[n];
      float* dst = out + n * CDIM + wn * 32 + 2 * (l & 3);
      const float* gsrc = d_g + n * CDIM + wn * 32 + 2 * (l & 3);
#pragma unroll
      for (int nt = 0; nt < 4; nt++) {
        float2 g2 = *(const float2*)(gsrc + nt * 8);
        float2 o = make_float2(acc[mt][nt][2 * h] * g2.x * mkv,
                               acc[mt][nt][2 * h + 1] * g2.y * mkv);
        *(float2*)(dst + nt * 8) = o;
      }
    }
  }
}

// ---------------- launch ----------------------------------------------------
extern "C" void kernel_launch(void* const* d_in, const int* in_sizes, int n_in,
                              void* d_out, int out_size) {
  const float* z        = (const float*)d_in[0];
  const int*   mask     = (const int*)  d_in[1];
  const float* ln_in_w  = (const float*)d_in[2];
  const float* ln_in_b  = (const float*)d_in[3];
  const float* ln_out_w = (const float*)d_in[4];
  const float* ln_out_b = (const float*)d_in[5];
  const float* Wpa = (const float*)d_in[6];
  const float* Wga = (const float*)d_in[7];
  const float* Wpb = (const float*)d_in[8];
  const float* Wgb = (const float*)d_in[9];
  const float* Wgo = (const float*)d_in[10];
  const float* Wpo = (const float*)d_in[11];
  float* out = (float*)d_out;

  cudaFuncSetAttribute(k_projmma, cudaFuncAttributeMaxDynamicSharedMemorySize, PROJ_SMEM);
  cudaFuncSetAttribute(k_einsum_mma, cudaFuncAttributeMaxDynamicSharedMemorySize, EIN_SMEM);
  cudaFuncSetAttribute(k_outmma, cudaFuncAttributeMaxDynamicSharedMemorySize, KO_SMEM);

  k_prew<<<dim3(8, 6), 256>>>(Wga, Wpa, Wgb, Wpb, Wgo, Wpo);
  k_projmma<<<NROWS / 64, 256, PROJ_SMEM>>>(z, mask, ln_in_w, ln_in_b);
  dim3 g2(LDIM / 128, LDIM / 128, CDIM);
  k_einsum_mma<<<g2, 256, EIN_SMEM>>>();
  dim3 g3(LDIM / 64, LDIM);
  k_outmma<<<g3, 256, KO_SMEM>>>(ln_out_w, ln_out_b, mask, out);
}